// round 4
// baseline (speedup 1.0000x reference)
#include <cuda_runtime.h>
#include <math.h>

// Qwen2.5 MoE expert router, fused: GEMM(logits) + softmax + top-2 + dispatch + aux loss.
// Round 4: packed fp32x2 FMA (FFMA2) GEMM — 2x fp32 FMA throughput, bit-exact fp32.
// out layout (fp32, reference return order):
//   [0, NE) dispatch | [NE, 2NE) combine | [2NE, 3NE) logits | [3NE, 4NE) probs
//   [4NE] aux_loss | [4NE+1, +2N) top_k_idx (float) | next 2N: top_k_probs_norm

#define D_DIM 2048
#define E_DIM 64
#define BM 128
#define BK 32
#define NTHREADS 128
#define TM 8            // tokens per thread (4 packed pairs)
#define TN 8            // experts per thread
#define KT (D_DIM / BK) // 64 k-tiles
#define A_STRIDE (BM + 4)   // 132 floats; 528B per k-row (16B aligned)
#define B_STRIDE (E_DIM + 4)// 68 floats; 272B per k-row (16B aligned)
#define L_STRIDE (E_DIM + 1)

#define A_ELEMS (BK * A_STRIDE)          // 4224
#define B_ELEMS (BK * B_STRIDE)          // 2176
#define L_ELEMS (BM * L_STRIDE)          // 8320
#define SPART_ELEMS (4 * E_DIM)          // 256
#define SMEM_ELEMS (L_ELEMS + SPART_ELEMS) // 8576 floats (> A+B = 6400)

typedef unsigned long long u64;

__device__ __forceinline__ u64 dup2(float v) {
    u64 r;
    asm("mov.b64 %0, {%1, %1};" : "=l"(r) : "f"(v));
    return r;
}
__device__ __forceinline__ void ffma2(u64& acc, u64 a, u64 b) {
    asm("fma.rn.f32x2 %0, %1, %2, %0;" : "+l"(acc) : "l"(a), "l"(b));
}
__device__ __forceinline__ void unpack2(u64 v, float& lo, float& hi) {
    asm("mov.b64 {%0, %1}, %2;" : "=f"(lo), "=f"(hi) : "l"(v));
}

__device__ float g_partials[512 * E_DIM];

__global__ __launch_bounds__(NTHREADS)
void router_fused_kernel(const float* __restrict__ x,
                         const float* __restrict__ w,
                         float* __restrict__ out,
                         int N)
{
    __shared__ float smem[SMEM_ELEMS];
    float* As = smem;               // [BK][BM+4] transposed, GEMM phase
    float* Bs = smem + A_ELEMS;     // [BK][E+4]  transposed, GEMM phase
    float* Lg = smem;               // [BM][E+1]  epilogue (aliases As/Bs)
    float* sPart = smem + L_ELEMS;  // [4][E]

    const int tid = threadIdx.x;
    const int block_row = blockIdx.x * BM;

    // compute-tile mapping: 8 expert-cols x 16 token-rows
    const int tc = tid & 7;        // expert col group
    const int tr = tid >> 3;       // token row group 0..15
    const int e0 = tc * TN;        // 0..56
    const int m0 = tr * TM;        // 0..120

    // global->smem staging mapping
    const int lk = (tid & 7) * 4;  // k offset 0..28
    const int lr = tid >> 3;       // row within 16-row group

    float4 aReg[8];   // A tile: 128x32 / 128 thr = 8 float4
    float4 bReg[4];   // B tile: 64x32 / 128 thr = 4 float4

    u64 acc[4][TN];   // 4 token-pairs x 8 experts, packed fp32x2
    #pragma unroll
    for (int i = 0; i < 4; i++)
        #pragma unroll
        for (int j = 0; j < TN; j++) acc[i][j] = 0ull;

    // ---- prologue: stage tile 0 ----
    #pragma unroll
    for (int p = 0; p < 8; p++) {
        int row = block_row + lr + 16 * p;
        aReg[p] = (row < N)
            ? *reinterpret_cast<const float4*>(x + (size_t)row * D_DIM + lk)
            : make_float4(0.f, 0.f, 0.f, 0.f);
    }
    #pragma unroll
    for (int p = 0; p < 4; p++) {
        int er = lr + 16 * p;
        bReg[p] = *reinterpret_cast<const float4*>(w + (size_t)er * D_DIM + lk);
    }

    for (int kt = 0; kt < KT; kt++) {
        __syncthreads();

        #pragma unroll
        for (int p = 0; p < 8; p++) {
            int m = lr + 16 * p;
            As[(lk + 0) * A_STRIDE + m] = aReg[p].x;
            As[(lk + 1) * A_STRIDE + m] = aReg[p].y;
            As[(lk + 2) * A_STRIDE + m] = aReg[p].z;
            As[(lk + 3) * A_STRIDE + m] = aReg[p].w;
        }
        #pragma unroll
        for (int p = 0; p < 4; p++) {
            int e = lr + 16 * p;
            Bs[(lk + 0) * B_STRIDE + e] = bReg[p].x;
            Bs[(lk + 1) * B_STRIDE + e] = bReg[p].y;
            Bs[(lk + 2) * B_STRIDE + e] = bReg[p].z;
            Bs[(lk + 3) * B_STRIDE + e] = bReg[p].w;
        }
        __syncthreads();

        if (kt + 1 < KT) {
            const int kbase = (kt + 1) * BK;
            #pragma unroll
            for (int p = 0; p < 8; p++) {
                int row = block_row + lr + 16 * p;
                aReg[p] = (row < N)
                    ? *reinterpret_cast<const float4*>(x + (size_t)row * D_DIM + kbase + lk)
                    : make_float4(0.f, 0.f, 0.f, 0.f);
            }
            #pragma unroll
            for (int p = 0; p < 4; p++) {
                int er = lr + 16 * p;
                bReg[p] = *reinterpret_cast<const float4*>(w + (size_t)er * D_DIM + kbase + lk);
            }
        }

        #pragma unroll 4
        for (int kk = 0; kk < BK; kk++) {
            // a pairs: 2x LDS.128, 4 lanes distinct + 8-way broadcast -> conflict-free
            ulonglong2 a01 = *reinterpret_cast<const ulonglong2*>(&As[kk * A_STRIDE + m0]);
            ulonglong2 a23 = *reinterpret_cast<const ulonglong2*>(&As[kk * A_STRIDE + m0 + 4]);
            u64 ap[4] = {a01.x, a01.y, a23.x, a23.y};
            // b scalars: 2x LDS.128 (4-way broadcast), duplicated via mov.b64 (ALU pipe)
            float4 b0 = *reinterpret_cast<const float4*>(&Bs[kk * B_STRIDE + e0]);
            float4 b1 = *reinterpret_cast<const float4*>(&Bs[kk * B_STRIDE + e0 + 4]);
            u64 bd[TN] = {dup2(b0.x), dup2(b0.y), dup2(b0.z), dup2(b0.w),
                          dup2(b1.x), dup2(b1.y), dup2(b1.z), dup2(b1.w)};
            #pragma unroll
            for (int i = 0; i < 4; i++)
                #pragma unroll
                for (int j = 0; j < TN; j++)
                    ffma2(acc[i][j], ap[i], bd[j]);
        }
    }

    // ---- epilogue: logits -> smem ----
    __syncthreads();
    #pragma unroll
    for (int i = 0; i < 4; i++)
        #pragma unroll
        for (int j = 0; j < TN; j++) {
            float lo, hi;
            unpack2(acc[i][j], lo, hi);
            Lg[(m0 + 2 * i)     * L_STRIDE + (e0 + j)] = lo;
            Lg[(m0 + 2 * i + 1) * L_STRIDE + (e0 + j)] = hi;
        }
    __syncthreads();

    const int warpId = tid >> 5;   // 0..3
    const int lane = tid & 31;
    const size_t NE = (size_t)N * E_DIM;
    const float NEG_INF = __int_as_float(0xff800000);

    float auxA = 0.f, auxB = 0.f;

    for (int tk = warpId; tk < BM; tk += 4) {
        int n = block_row + tk;
        if (n >= N) continue;  // warp-uniform

        float v0 = Lg[tk * L_STRIDE + lane];
        float v1 = Lg[tk * L_STRIDE + lane + 32];

        float mx = fmaxf(v0, v1);
        #pragma unroll
        for (int o = 16; o; o >>= 1) mx = fmaxf(mx, __shfl_xor_sync(0xffffffffu, mx, o));
        float x0 = expf(v0 - mx), x1 = expf(v1 - mx);
        float s = x0 + x1;
        #pragma unroll
        for (int o = 16; o; o >>= 1) s += __shfl_xor_sync(0xffffffffu, s, o);
        float p0 = x0 / s, p1 = x1 / s;
        auxA += p0; auxB += p1;

        // top-1 (tie -> smallest index)
        float bvv; int bi;
        if (p0 >= p1) { bvv = p0; bi = lane; } else { bvv = p1; bi = lane + 32; }
        #pragma unroll
        for (int o = 16; o; o >>= 1) {
            float ov = __shfl_xor_sync(0xffffffffu, bvv, o);
            int   oi = __shfl_xor_sync(0xffffffffu, bi, o);
            if (ov > bvv || (ov == bvv && oi < bi)) { bvv = ov; bi = oi; }
        }
        // top-2
        float c0 = (lane == bi) ? NEG_INF : p0;
        float c1 = (lane + 32 == bi) ? NEG_INF : p1;
        float sv; int si;
        if (c0 >= c1) { sv = c0; si = lane; } else { sv = c1; si = lane + 32; }
        #pragma unroll
        for (int o = 16; o; o >>= 1) {
            float ov = __shfl_xor_sync(0xffffffffu, sv, o);
            int   oi = __shfl_xor_sync(0xffffffffu, si, o);
            if (ov > sv || (ov == sv && oi < si)) { sv = ov; si = oi; }
        }

        float tsum = bvv + sv;
        float pn1 = bvv / tsum, pn2 = sv / tsum;

        size_t rowL = (size_t)n * E_DIM;
        out[2 * NE + rowL + lane]      = v0;
        out[2 * NE + rowL + lane + 32] = v1;
        out[3 * NE + rowL + lane]      = p0;
        out[3 * NE + rowL + lane + 32] = p1;
        float d0 = (lane == bi) ? pn1 : ((lane == si) ? pn2 : 0.f);
        float d1 = (lane + 32 == bi) ? pn1 : ((lane + 32 == si) ? pn2 : 0.f);
        out[rowL + lane]           = d0;
        out[rowL + lane + 32]      = d1;
        out[NE + rowL + lane]      = d0;
        out[NE + rowL + lane + 32] = d1;
        if (lane == 0) {
            size_t o5 = 4 * NE + 1 + (size_t)n * 2;
            out[o5]     = (float)bi;
            out[o5 + 1] = (float)si;
            size_t o6 = 4 * NE + 1 + (size_t)N * 2 + (size_t)n * 2;
            out[o6]     = pn1;
            out[o6 + 1] = pn2;
        }
    }

    sPart[warpId * E_DIM + lane]      = auxA;
    sPart[warpId * E_DIM + lane + 32] = auxB;
    __syncthreads();
    if (tid < E_DIM) {
        float ssum = 0.f;
        #pragma unroll
        for (int wd = 0; wd < 4; wd++) ssum += sPart[wd * E_DIM + tid];
        g_partials[blockIdx.x * E_DIM + tid] = ssum;
    }
}

__global__ void aux_loss_kernel(float* __restrict__ out, int N, int nBlocks)
{
    __shared__ float sp[4][E_DIM];
    __shared__ float sq[E_DIM];
    int e = threadIdx.x & 63;
    int q = threadIdx.x >> 6;   // 0..3
    float s = 0.f;
    for (int b = q; b < nBlocks; b += 4) s += g_partials[b * E_DIM + e];
    sp[q][e] = s;
    __syncthreads();
    if (threadIdx.x < E_DIM) {
        float t = sp[0][e] + sp[1][e] + sp[2][e] + sp[3][e];
        float m = t / (float)N;
        sq[e] = m * m;
    }
    __syncthreads();
    if (threadIdx.x == 0) {
        float a = 0.f;
        #pragma unroll
        for (int i = 0; i < E_DIM; i++) a += sq[i];
        out[(size_t)4 * N * E_DIM] = a;  // mean_e(E*p^2) = sum_e p^2
    }
}

extern "C" void kernel_launch(void* const* d_in, const int* in_sizes, int n_in,
                              void* d_out, int out_size)
{
    const float* x = (const float*)d_in[0];   // [N, 2048]
    const float* w = (const float*)d_in[1];   // [64, 2048]
    float* out = (float*)d_out;

    int N = in_sizes[0] / D_DIM;              // 16384
    int nBlocks = (N + BM - 1) / BM;          // 128

    router_fused_kernel<<<nBlocks, NTHREADS>>>(x, w, out, N);
    aux_loss_kernel<<<1, 256>>>(out, N, nBlocks);
}

// round 5
// speedup vs baseline: 1.0555x; 1.0555x over previous
#include <cuda_runtime.h>
#include <math.h>

// Qwen2.5 MoE expert router, fused single kernel:
// GEMM(logits) + softmax + top-2 + dispatch scatter + aux loss (last-block reduction).
// Round 5: 148-block uneven-M decomposition (all SMs busy), BM=112, TM=7, TN=4.
// out layout (fp32, reference return order):
//   [0, NE) dispatch | [NE, 2NE) combine | [2NE, 3NE) logits | [3NE, 4NE) probs
//   [4NE] aux_loss | [4NE+1, +2N) top_k_idx (as float) | next 2N: top_k_probs_norm

#define D_DIM 2048
#define E_DIM 64
#define NBLK 148
#define BM 112              // token tile (16 groups x 7)
#define BK 32
#define NTHREADS 256
#define TM 7                // tokens per thread (group padded to 8 smem slots)
#define TN 4                // experts per thread
#define KT (D_DIM / BK)     // 64 k-tiles
#define A_COLS 128          // 16 groups x 8 slots
#define A_STRIDE (A_COLS + 4)   // 132 (mult of 4 -> LDS.128 alignment holds)
#define B_STRIDE (E_DIM + 4)    // 68
#define L_STRIDE (E_DIM + 1)    // 65

#define A_ELEMS (BK * A_STRIDE)            // 4224
#define B_ELEMS (BK * B_STRIDE)            // 2176
#define L_ELEMS (BM * L_STRIDE)            // 7280
#define SPART_ELEMS (8 * E_DIM)            // 512
#define SMEM_ELEMS (L_ELEMS + SPART_ELEMS) // 7792 > A+B = 6400

#define A_F4 (BM * (BK / 4))   // 896 float4 per A tile
#define B_F4 (E_DIM * (BK / 4))// 512 float4 per B tile

__device__ float g_partials[NBLK * E_DIM];
__device__ unsigned int g_count = 0;

__global__ __launch_bounds__(NTHREADS)
void router_fused_kernel(const float* __restrict__ x,
                         const float* __restrict__ w,
                         float* __restrict__ out,
                         int N)
{
    __shared__ float smem[SMEM_ELEMS];
    __shared__ int sIsLast;
    float* As = smem;               // [BK][A_COLS+4] transposed, GEMM phase
    float* Bs = smem + A_ELEMS;     // [BK][E+4]      transposed, GEMM phase
    float* Lg = smem;               // [BM][E+1]      epilogue (aliases As/Bs)
    float* sPart = smem + L_ELEMS;  // [8][E]

    const int tid = threadIdx.x;
    const int bid = blockIdx.x;
    // uneven token partition: all 148 SMs get 110-111 tokens
    const int n0 = (bid * (N / 4)) / (NBLK / 4);          // bid*4096/37
    const int n1 = ((bid + 1) * (N / 4)) / (NBLK / 4);

    // compute-tile mapping
    const int tc = tid & 15;        // expert group
    const int tr = tid >> 4;        // token group 0..15
    const int e0 = tc * TN;
    const int m0g = tr * 8;         // smem column base (8-slot aligned)
    const int tok0 = tr * TM;       // first token (0..105)

    float4 aReg[4];                 // A staging: up to 896/256 = 3.5 -> 4 slots
    float4 bReg[2];

    float acc[TM][TN];
    #pragma unroll
    for (int i = 0; i < TM; i++)
        #pragma unroll
        for (int j = 0; j < TN; j++) acc[i][j] = 0.f;

    // ---- prologue: stage tile 0 into registers ----
    #pragma unroll
    for (int p = 0; p < 4; p++) {
        int idx = tid + 256 * p;
        if (idx < A_F4) {
            int row = idx >> 3, kseg = idx & 7;
            int n = n0 + row;
            aReg[p] = (n < n1)
                ? *reinterpret_cast<const float4*>(x + (size_t)n * D_DIM + kseg * 4)
                : make_float4(0.f, 0.f, 0.f, 0.f);
        }
    }
    #pragma unroll
    for (int p = 0; p < 2; p++) {
        int idx = tid + 256 * p;
        int er = idx >> 3, kseg = idx & 7;
        bReg[p] = *reinterpret_cast<const float4*>(w + (size_t)er * D_DIM + kseg * 4);
    }

    for (int kt = 0; kt < KT; kt++) {
        __syncthreads();

        #pragma unroll
        for (int p = 0; p < 4; p++) {
            int idx = tid + 256 * p;
            if (idx < A_F4) {
                int row = idx >> 3, kseg = idx & 7;
                int col = (row / 7) * 8 + (row % 7);   // 7-token groups in 8 slots
                As[(kseg * 4 + 0) * A_STRIDE + col] = aReg[p].x;
                As[(kseg * 4 + 1) * A_STRIDE + col] = aReg[p].y;
                As[(kseg * 4 + 2) * A_STRIDE + col] = aReg[p].z;
                As[(kseg * 4 + 3) * A_STRIDE + col] = aReg[p].w;
            }
        }
        #pragma unroll
        for (int p = 0; p < 2; p++) {
            int idx = tid + 256 * p;
            int er = idx >> 3, kseg = idx & 7;
            Bs[(kseg * 4 + 0) * B_STRIDE + er] = bReg[p].x;
            Bs[(kseg * 4 + 1) * B_STRIDE + er] = bReg[p].y;
            Bs[(kseg * 4 + 2) * B_STRIDE + er] = bReg[p].z;
            Bs[(kseg * 4 + 3) * B_STRIDE + er] = bReg[p].w;
        }
        __syncthreads();

        if (kt + 1 < KT) {
            const int kbase = (kt + 1) * BK;
            #pragma unroll
            for (int p = 0; p < 4; p++) {
                int idx = tid + 256 * p;
                if (idx < A_F4) {
                    int row = idx >> 3, kseg = idx & 7;
                    int n = n0 + row;
                    aReg[p] = (n < n1)
                        ? *reinterpret_cast<const float4*>(x + (size_t)n * D_DIM + kbase + kseg * 4)
                        : make_float4(0.f, 0.f, 0.f, 0.f);
                }
            }
            #pragma unroll
            for (int p = 0; p < 2; p++) {
                int idx = tid + 256 * p;
                int er = idx >> 3, kseg = idx & 7;
                bReg[p] = *reinterpret_cast<const float4*>(w + (size_t)er * D_DIM + kbase + kseg * 4);
            }
        }

        #pragma unroll 4
        for (int kk = 0; kk < BK; kk++) {
            // a: 2x LDS.128 (aligned: A_STRIDE%4==0, m0g%4==0); use 7 of 8
            float4 a0 = *reinterpret_cast<const float4*>(&As[kk * A_STRIDE + m0g]);
            float4 a1 = *reinterpret_cast<const float4*>(&As[kk * A_STRIDE + m0g + 4]);
            float4 b  = *reinterpret_cast<const float4*>(&Bs[kk * B_STRIDE + e0]);
            float av[TM] = {a0.x, a0.y, a0.z, a0.w, a1.x, a1.y, a1.z};
            float bv[TN] = {b.x, b.y, b.z, b.w};
            #pragma unroll
            for (int i = 0; i < TM; i++)
                #pragma unroll
                for (int j = 0; j < TN; j++)
                    acc[i][j] = fmaf(av[i], bv[j], acc[i][j]);
        }
    }

    // ---- epilogue: logits -> smem ----
    __syncthreads();
    #pragma unroll
    for (int i = 0; i < TM; i++)
        #pragma unroll
        for (int j = 0; j < TN; j++)
            Lg[(tok0 + i) * L_STRIDE + (e0 + j)] = acc[i][j];
    __syncthreads();

    const int warpId = tid >> 5;   // 0..7
    const int lane = tid & 31;
    const size_t NE = (size_t)N * E_DIM;
    const float NEG_INF = __int_as_float(0xff800000);

    float auxA = 0.f, auxB = 0.f;

    for (int tk = warpId; tk < BM; tk += 8) {
        int n = n0 + tk;
        if (n >= n1) continue;   // warp-uniform

        float v0 = Lg[tk * L_STRIDE + lane];
        float v1 = Lg[tk * L_STRIDE + lane + 32];

        float mx = fmaxf(v0, v1);
        #pragma unroll
        for (int o = 16; o; o >>= 1) mx = fmaxf(mx, __shfl_xor_sync(0xffffffffu, mx, o));
        float x0 = expf(v0 - mx), x1 = expf(v1 - mx);
        float s = x0 + x1;
        #pragma unroll
        for (int o = 16; o; o >>= 1) s += __shfl_xor_sync(0xffffffffu, s, o);
        float p0 = x0 / s, p1 = x1 / s;
        auxA += p0; auxB += p1;

        // top-1 (tie -> smallest index, matching jax.lax.top_k)
        float bvv; int bi;
        if (p0 >= p1) { bvv = p0; bi = lane; } else { bvv = p1; bi = lane + 32; }
        #pragma unroll
        for (int o = 16; o; o >>= 1) {
            float ov = __shfl_xor_sync(0xffffffffu, bvv, o);
            int   oi = __shfl_xor_sync(0xffffffffu, bi, o);
            if (ov > bvv || (ov == bvv && oi < bi)) { bvv = ov; bi = oi; }
        }
        // top-2
        float c0 = (lane == bi) ? NEG_INF : p0;
        float c1 = (lane + 32 == bi) ? NEG_INF : p1;
        float sv; int si;
        if (c0 >= c1) { sv = c0; si = lane; } else { sv = c1; si = lane + 32; }
        #pragma unroll
        for (int o = 16; o; o >>= 1) {
            float ov = __shfl_xor_sync(0xffffffffu, sv, o);
            int   oi = __shfl_xor_sync(0xffffffffu, si, o);
            if (ov > sv || (ov == sv && oi < si)) { sv = ov; si = oi; }
        }

        float tsum = bvv + sv;
        float pn1 = bvv / tsum, pn2 = sv / tsum;

        size_t rowL = (size_t)n * E_DIM;
        out[2 * NE + rowL + lane]      = v0;
        out[2 * NE + rowL + lane + 32] = v1;
        out[3 * NE + rowL + lane]      = p0;
        out[3 * NE + rowL + lane + 32] = p1;
        float d0 = (lane == bi) ? pn1 : ((lane == si) ? pn2 : 0.f);
        float d1 = (lane + 32 == bi) ? pn1 : ((lane + 32 == si) ? pn2 : 0.f);
        out[rowL + lane]           = d0;
        out[rowL + lane + 32]      = d1;
        out[NE + rowL + lane]      = d0;
        out[NE + rowL + lane + 32] = d1;
        if (lane == 0) {
            size_t o5 = 4 * NE + 1 + (size_t)n * 2;
            out[o5]     = (float)bi;
            out[o5 + 1] = (float)si;
            size_t o6 = 4 * NE + 1 + (size_t)N * 2 + (size_t)n * 2;
            out[o6]     = pn1;
            out[o6 + 1] = pn2;
        }
    }

    // per-block per-expert prob sums (deterministic: fixed warp order)
    sPart[warpId * E_DIM + lane]      = auxA;
    sPart[warpId * E_DIM + lane + 32] = auxB;
    __syncthreads();
    if (tid < E_DIM) {
        float ssum = 0.f;
        #pragma unroll
        for (int wd = 0; wd < 8; wd++) ssum += sPart[wd * E_DIM + tid];
        g_partials[bid * E_DIM + tid] = ssum;
    }
    __threadfence();
    if (tid == 0) {
        unsigned int prev = atomicAdd(&g_count, 1u);
        sIsLast = (prev == (unsigned int)(gridDim.x - 1)) ? 1 : 0;
    }
    __syncthreads();

    // ---- last block: aux loss reduction (value independent of which block) ----
    if (sIsLast) {
        __threadfence();
        int e = tid & 63;
        int q = tid >> 6;   // 0..3
        float s = 0.f;
        for (int b = q; b < NBLK; b += 4) s += g_partials[b * E_DIM + e];
        sPart[q * E_DIM + e] = s;   // reuse smem
        __syncthreads();
        if (tid < E_DIM) {
            float t = sPart[0 * E_DIM + tid] + sPart[1 * E_DIM + tid]
                    + sPart[2 * E_DIM + tid] + sPart[3 * E_DIM + tid];
            float m = t / (float)N;
            Lg[tid] = m * m;        // reuse smem
        }
        __syncthreads();
        if (tid == 0) {
            float a = 0.f;
            #pragma unroll
            for (int i = 0; i < E_DIM; i++) a += Lg[i];
            out[4 * NE] = a;        // mean_e(E*p^2) = sum_e p^2
            g_count = 0;            // reset for next graph replay
        }
    }
}

extern "C" void kernel_launch(void* const* d_in, const int* in_sizes, int n_in,
                              void* d_out, int out_size)
{
    const float* x = (const float*)d_in[0];   // [N, 2048]
    const float* w = (const float*)d_in[1];   // [64, 2048]
    float* out = (float*)d_out;

    int N = in_sizes[0] / D_DIM;              // 16384
    router_fused_kernel<<<NBLK, NTHREADS>>>(x, w, out, N);
}